// round 11
// baseline (speedup 1.0000x reference)
#include <cuda_runtime.h>
#include <cuda_bf16.h>
#include <cuda_fp8.h>
#include <cstdint>

// Problem dims (fixed by reference)
#define T_DIM 8192
#define H_DIM 4096            // both K (reduction) and N (output)
#define FP8_MAX_V 448.0f

// ---------------------------------------------------------------------------
// Scratch (allocation-free per harness rules)
// ---------------------------------------------------------------------------
__device__ __align__(16) uint8_t g_xq8[(size_t)T_DIM * H_DIM];    // 32 MB, [t][k] e4m3
__device__ __align__(16) uint8_t g_wq8t[(size_t)H_DIM * H_DIM];   // 16 MB, [n][k] e4m3 (w^T)
__device__ float g_xscale[T_DIM];

// ---------------------------------------------------------------------------
// Helpers
// ---------------------------------------------------------------------------
__device__ __forceinline__ uint32_t smem_u32(const void* p) {
    uint32_t a;
    asm("{ .reg .u64 t; cvta.to.shared.u64 t, %1; cvt.u32.u64 %0, t; }" : "=r"(a) : "l"(p));
    return a;
}

#define CP_ASYNC16(dst, src) \
    asm volatile("cp.async.cg.shared.global [%0], [%1], 16;" :: "r"(dst), "l"(src) : "memory")
#define CP_COMMIT() asm volatile("cp.async.commit_group;" ::: "memory")
#define CP_WAIT2()  asm volatile("cp.async.wait_group 2;" ::: "memory")

#define LDMATRIX_X4(r0, r1, r2, r3, addr) \
    asm volatile("ldmatrix.sync.aligned.m8n8.x4.shared.b16 {%0,%1,%2,%3}, [%4];" \
                 : "=r"(r0), "=r"(r1), "=r"(r2), "=r"(r3) : "r"(addr))

__device__ __forceinline__ void mma_e4m3(float* d, const uint32_t* a, const uint32_t* b) {
    asm volatile(
        "mma.sync.aligned.m16n8k32.row.col.f32.e4m3.e4m3.f32 "
        "{%0,%1,%2,%3}, {%4,%5,%6,%7}, {%8,%9}, {%0,%1,%2,%3};"
        : "+f"(d[0]), "+f"(d[1]), "+f"(d[2]), "+f"(d[3])
        : "r"(a[0]), "r"(a[1]), "r"(a[2]), "r"(a[3]), "r"(b[0]), "r"(b[1]));
}

__device__ __forceinline__ uint8_t fp8b(float v) {
    return (uint8_t)__nv_cvt_float_to_fp8(v, __NV_SATFINITE, __NV_E4M3);
}

// ---------------------------------------------------------------------------
// Kernel 1: fused quantization.
//   blocks [0, 8192):      per-token amax + quantize x row -> g_xq8
//   blocks [8192, 12288):  64x64 w tile quantize+transpose -> g_wq8t
// ---------------------------------------------------------------------------
#define QX_BLOCKS T_DIM                          // 8192
#define QW_BLOCKS ((H_DIM / 64) * (H_DIM / 64))  // 4096

__global__ void __launch_bounds__(256) quant_all(const float* __restrict__ x,
                                                 const float* __restrict__ w) {
    if (blockIdx.x < QX_BLOCKS) {
        // ----- x row quantization -----
        const int row = blockIdx.x;
        const float* xr = x + (size_t)row * H_DIM;

        float amax = 0.f;
        float4 vv[4];
        #pragma unroll
        for (int j = 0; j < 4; j++) {
            vv[j] = *reinterpret_cast<const float4*>(xr + threadIdx.x * 4 + j * 1024);
            amax = fmaxf(amax, fmaxf(fmaxf(fabsf(vv[j].x), fabsf(vv[j].y)),
                                     fmaxf(fabsf(vv[j].z), fabsf(vv[j].w))));
        }
        #pragma unroll
        for (int o = 16; o; o >>= 1)
            amax = fmaxf(amax, __shfl_xor_sync(0xffffffffu, amax, o));

        __shared__ float warpmax[8];
        __shared__ float s_scale;
        int wid = threadIdx.x >> 5, lane = threadIdx.x & 31;
        if (lane == 0) warpmax[wid] = amax;
        __syncthreads();
        if (wid == 0) {
            float m = (lane < 8) ? warpmax[lane] : 0.f;
            #pragma unroll
            for (int o = 4; o; o >>= 1)
                m = fmaxf(m, __shfl_xor_sync(0xffffffffu, m, o));
            if (lane == 0) {
                float s = fmaxf(m / FP8_MAX_V, 1e-12f);
                s_scale = s;
                g_xscale[row] = s;
            }
        }
        __syncthreads();
        const float scale = s_scale;

        #pragma unroll
        for (int j = 0; j < 4; j++) {
            int c = threadIdx.x * 4 + j * 1024;
            float4 v = vv[j];
            uint32_t p = (uint32_t)fp8b(v.x / scale)
                       | ((uint32_t)fp8b(v.y / scale) << 8)
                       | ((uint32_t)fp8b(v.z / scale) << 16)
                       | ((uint32_t)fp8b(v.w / scale) << 24);
            *reinterpret_cast<uint32_t*>(g_xq8 + (size_t)row * H_DIM + c) = p;
        }
    } else {
        // ----- w quantize + transpose (register-blocked 4x4) -----
        const int wb = blockIdx.x - QX_BLOCKS;
        const int h0 = (wb & 63) * 64 + (threadIdx.x & 15) * 4;
        const int k0 = (wb >> 6) * 64 + (threadIdx.x >> 4) * 4;

        uint8_t b[4][4];
        #pragma unroll
        for (int j = 0; j < 4; j++) {
            float4 v = *reinterpret_cast<const float4*>(w + (size_t)(k0 + j) * H_DIM + h0);
            b[j][0] = fp8b(v.x); b[j][1] = fp8b(v.y);
            b[j][2] = fp8b(v.z); b[j][3] = fp8b(v.w);
        }
        #pragma unroll
        for (int i = 0; i < 4; i++) {
            uint32_t p = (uint32_t)b[0][i] | ((uint32_t)b[1][i] << 8)
                       | ((uint32_t)b[2][i] << 16) | ((uint32_t)b[3][i] << 24);
            *reinterpret_cast<uint32_t*>(g_wq8t + (size_t)(h0 + i) * H_DIM + k0) = p;
        }
    }
}

// ---------------------------------------------------------------------------
// Kernel 2: fp8 mma.sync GEMM.  y[t,n] = (sum_k xq[t,k]*wqt[n,k]) * xscale[t]*wscale
// CTA 128x256, BK=128, 4-stage cp.async pipeline, 8 warps (2M x 4N), warp 64x64.
// CUTLASS-style schedule: barrier at kk=3, covered by mma(3); next-stage
// frag(0) loaded right after the barrier, hidden under mma(3).
// ---------------------------------------------------------------------------
#define BM 128
#define BN 256
#define BK 128
#define STAGES 4
#define STG_A (BM * BK)                   // 16384
#define STG_B (BN * BK)                   // 32768
#define STG_BYTES (STG_A + STG_B)         // 49152
#define GEMM_SMEM (1024 + STAGES * STG_BYTES)   // 197632

__global__ void __launch_bounds__(256, 1) gemm_f8(float* __restrict__ out,
                                                  const float* __restrict__ wscale_p) {
    extern __shared__ char dyn_smem[];
    const uint32_t base = (smem_u32(dyn_smem) + 1023) & ~1023u;

    const int tid = threadIdx.x;
    const int wid = tid >> 5, lane = tid & 31;
    const int warp_m = wid & 1;     // 2 warps along M (64 rows each)
    const int warp_n = wid >> 1;    // 4 warps along N (64 cols each)

    // 16 consecutive bids share one M-band: A reuse, B fully L2-resident (16MB)
    const int m_tile = blockIdx.x >> 4;     // 0..63
    const int n_tile = blockIdx.x & 15;     // 0..15

    const uint8_t* Ag = g_xq8 + (size_t)m_tile * BM * H_DIM;
    const uint8_t* Bg = g_wq8t + (size_t)n_tile * BN * H_DIM;

    float acc[4][8][4];
    #pragma unroll
    for (int a = 0; a < 4; a++)
        #pragma unroll
        for (int b = 0; b < 8; b++)
            #pragma unroll
            for (int c = 0; c < 4; c++) acc[a][b][c] = 0.f;

    // Load K-slab t into stage s. XOR swizzle (16B chunk ^ row&7) -> conflict-free LDSM.
    auto load_tile = [&](int t, int s) {
        const uint32_t sa = base + s * STG_BYTES;
        const uint32_t sb = sa + STG_A;
        const int koff = t * BK;
        #pragma unroll
        for (int j = 0; j < 4; j++) {           // A: 1024 x 16B
            int idx = tid + j * 256;
            int r = idx >> 3, c = idx & 7;
            CP_ASYNC16(sa + r * 128 + ((c ^ (r & 7)) << 4),
                       Ag + (size_t)r * H_DIM + koff + (c << 4));
        }
        #pragma unroll
        for (int j = 0; j < 8; j++) {           // B: 2048 x 16B
            int idx = tid + j * 256;
            int r = idx >> 3, c = idx & 7;
            CP_ASYNC16(sb + r * 128 + ((c ^ (r & 7)) << 4),
                       Bg + (size_t)r * H_DIM + koff + (c << 4));
        }
        CP_COMMIT();
    };

    // Fragment load for one k32 step (kk in 0..3) from stage base (sa, sb).
    auto load_frags = [&](uint32_t sa, uint32_t sb, int kk,
                          uint32_t (*af)[4], uint32_t (*bf)[2]) {
        #pragma unroll
        for (int mi = 0; mi < 4; mi++) {
            int r = warp_m * 64 + mi * 16 + (lane & 15);
            int ch = (kk * 2 + (lane >> 4)) ^ (r & 7);
            LDMATRIX_X4(af[mi][0], af[mi][1], af[mi][2], af[mi][3],
                        sa + r * 128 + (ch << 4));
        }
        #pragma unroll
        for (int g = 0; g < 4; g++) {           // each x4 covers 2 n-groups of 8
            int n = warp_n * 64 + g * 16 + (lane & 15);
            int ch = (kk * 2 + (lane >> 4)) ^ (n & 7);
            uint32_t t0, t1, t2, t3;
            LDMATRIX_X4(t0, t1, t2, t3, sb + n * 128 + (ch << 4));
            bf[g * 2][0] = t0;     bf[g * 2][1] = t2;
            bf[g * 2 + 1][0] = t1; bf[g * 2 + 1][1] = t3;
        }
    };

    const int NKT = H_DIM / BK;   // 32

    // Prologue: fill stages 0..2; make tile 0 visible; preload frag(0).
    #pragma unroll
    for (int p = 0; p < STAGES - 1; p++) load_tile(p, p);
    CP_WAIT2();
    __syncthreads();

    uint32_t af[2][4][4];
    uint32_t bf[2][8][2];
    load_frags(base, base + STG_A, 0, af[0], bf[0]);

    for (int i = 0; i < NKT; i++) {
        const int s = i & (STAGES - 1);
        const uint32_t sa = base + s * STG_BYTES;
        const uint32_t sb = sa + STG_A;

        // Prefetch tile i+3 into stage (i+3)&3. That stage's reads finished
        // in iter i-1 and are fenced by iter i-1's kk=3 __syncthreads.
        const int nxt = i + STAGES - 1;
        if (nxt < NKT) load_tile(nxt, nxt & (STAGES - 1));

        #pragma unroll
        for (int kk = 0; kk < 4; kk++) {
            const int cur = kk & 1;
            if (kk < 3) {
                load_frags(sa, sb, kk + 1, af[cur ^ 1], bf[cur ^ 1]);
            } else {
                // Tile i+1 complete in every thread (groups i+1..i+3 outstanding,
                // wait_group 2) and made visible by the barrier. mma(3)'s operands
                // are already in registers, so the barrier is covered by MMA work.
                CP_WAIT2();
                __syncthreads();
                if (i + 1 < NKT) {
                    const uint32_t na = base + ((i + 1) & (STAGES - 1)) * STG_BYTES;
                    load_frags(na, na + STG_A, 0, af[cur ^ 1], bf[cur ^ 1]);
                }
            }
            #pragma unroll
            for (int mi = 0; mi < 4; mi++)
                #pragma unroll
                for (int ni = 0; ni < 8; ni++)
                    mma_e4m3(acc[mi][ni], af[cur][mi], bf[cur][ni]);
        }
    }

    // Epilogue: scale by xscale[row]*wscale, store fp32
    const float ws = wscale_p[0];
    const int row_base = m_tile * BM + warp_m * 64;
    const int col_base = n_tile * BN + warp_n * 64;
    #pragma unroll
    for (int mi = 0; mi < 4; mi++) {
        int r0 = row_base + mi * 16 + (lane >> 2);
        float s0 = g_xscale[r0] * ws;
        float s1 = g_xscale[r0 + 8] * ws;
        float* o0 = out + (size_t)r0 * H_DIM + col_base + ((lane & 3) << 1);
        float* o1 = o0 + (size_t)8 * H_DIM;
        #pragma unroll
        for (int ni = 0; ni < 8; ni++) {
            *reinterpret_cast<float2*>(o0 + ni * 8) =
                make_float2(acc[mi][ni][0] * s0, acc[mi][ni][1] * s0);
            *reinterpret_cast<float2*>(o1 + ni * 8) =
                make_float2(acc[mi][ni][2] * s1, acc[mi][ni][3] * s1);
        }
    }
}

// ---------------------------------------------------------------------------
extern "C" void kernel_launch(void* const* d_in, const int* in_sizes, int n_in,
                              void* d_out, int out_size) {
    const float* x = (const float*)d_in[0];        // [8192, 4096] fp32
    const float* w = (const float*)d_in[1];        // [4096, 4096] fp32
    const float* wscale = (const float*)d_in[2];   // [1] fp32
    float* out = (float*)d_out;                    // [8192, 4096] fp32

    cudaFuncSetAttribute(gemm_f8, cudaFuncAttributeMaxDynamicSharedMemorySize, GEMM_SMEM);

    quant_all<<<QX_BLOCKS + QW_BLOCKS, 256>>>(x, w);

    const int num_ctas = (T_DIM / BM) * (H_DIM / BN);  // 64 * 16 = 1024
    gemm_f8<<<num_ctas, 256, GEMM_SMEM>>>(out, wscale);
}

// round 12
// speedup vs baseline: 1.1136x; 1.1136x over previous
#include <cuda_runtime.h>
#include <cuda_bf16.h>
#include <cuda_fp8.h>
#include <cstdint>

// Problem dims (fixed by reference)
#define T_DIM 8192
#define H_DIM 4096            // both K (reduction) and N (output)
#define FP8_MAX_V 448.0f

// ---------------------------------------------------------------------------
// Scratch (allocation-free per harness rules)
// ---------------------------------------------------------------------------
__device__ __align__(16) uint8_t g_xq8[(size_t)T_DIM * H_DIM];    // 32 MB, [t][k] e4m3
__device__ __align__(16) uint8_t g_wq8t[(size_t)H_DIM * H_DIM];   // 16 MB, [n][k] e4m3 (w^T)
__device__ float g_xscale[T_DIM];

// ---------------------------------------------------------------------------
// Helpers
// ---------------------------------------------------------------------------
__device__ __forceinline__ uint32_t smem_u32(const void* p) {
    uint32_t a;
    asm("{ .reg .u64 t; cvta.to.shared.u64 t, %1; cvt.u32.u64 %0, t; }" : "=r"(a) : "l"(p));
    return a;
}

#define CP_ASYNC16(dst, src) \
    asm volatile("cp.async.cg.shared.global [%0], [%1], 16;" :: "r"(dst), "l"(src) : "memory")
#define CP_COMMIT() asm volatile("cp.async.commit_group;" ::: "memory")
#define CP_WAIT1()  asm volatile("cp.async.wait_group 1;" ::: "memory")

#define LDMATRIX_X4(r0, r1, r2, r3, addr) \
    asm volatile("ldmatrix.sync.aligned.m8n8.x4.shared.b16 {%0,%1,%2,%3}, [%4];" \
                 : "=r"(r0), "=r"(r1), "=r"(r2), "=r"(r3) : "r"(addr))

__device__ __forceinline__ void mma_e4m3(float* d, const uint32_t* a, const uint32_t* b) {
    asm volatile(
        "mma.sync.aligned.m16n8k32.row.col.f32.e4m3.e4m3.f32 "
        "{%0,%1,%2,%3}, {%4,%5,%6,%7}, {%8,%9}, {%0,%1,%2,%3};"
        : "+f"(d[0]), "+f"(d[1]), "+f"(d[2]), "+f"(d[3])
        : "r"(a[0]), "r"(a[1]), "r"(a[2]), "r"(a[3]), "r"(b[0]), "r"(b[1]));
}

__device__ __forceinline__ uint8_t fp8b(float v) {
    return (uint8_t)__nv_cvt_float_to_fp8(v, __NV_SATFINITE, __NV_E4M3);
}

// ---------------------------------------------------------------------------
// Kernel 1: fused quantization.
//   blocks [0, 8192):      per-token amax + quantize x row -> g_xq8
//   blocks [8192, 12288):  64x64 w tile quantize+transpose -> g_wq8t
// ---------------------------------------------------------------------------
#define QX_BLOCKS T_DIM                          // 8192
#define QW_BLOCKS ((H_DIM / 64) * (H_DIM / 64))  // 4096

__global__ void __launch_bounds__(256) quant_all(const float* __restrict__ x,
                                                 const float* __restrict__ w) {
    if (blockIdx.x < QX_BLOCKS) {
        // ----- x row quantization -----
        const int row = blockIdx.x;
        const float* xr = x + (size_t)row * H_DIM;

        float amax = 0.f;
        float4 vv[4];
        #pragma unroll
        for (int j = 0; j < 4; j++) {
            vv[j] = *reinterpret_cast<const float4*>(xr + threadIdx.x * 4 + j * 1024);
            amax = fmaxf(amax, fmaxf(fmaxf(fabsf(vv[j].x), fabsf(vv[j].y)),
                                     fmaxf(fabsf(vv[j].z), fabsf(vv[j].w))));
        }
        #pragma unroll
        for (int o = 16; o; o >>= 1)
            amax = fmaxf(amax, __shfl_xor_sync(0xffffffffu, amax, o));

        __shared__ float warpmax[8];
        __shared__ float s_scale;
        int wid = threadIdx.x >> 5, lane = threadIdx.x & 31;
        if (lane == 0) warpmax[wid] = amax;
        __syncthreads();
        if (wid == 0) {
            float m = (lane < 8) ? warpmax[lane] : 0.f;
            #pragma unroll
            for (int o = 4; o; o >>= 1)
                m = fmaxf(m, __shfl_xor_sync(0xffffffffu, m, o));
            if (lane == 0) {
                float s = fmaxf(m / FP8_MAX_V, 1e-12f);
                s_scale = s;
                g_xscale[row] = s;
            }
        }
        __syncthreads();
        const float scale = s_scale;

        #pragma unroll
        for (int j = 0; j < 4; j++) {
            int c = threadIdx.x * 4 + j * 1024;
            float4 v = vv[j];
            uint32_t p = (uint32_t)fp8b(v.x / scale)
                       | ((uint32_t)fp8b(v.y / scale) << 8)
                       | ((uint32_t)fp8b(v.z / scale) << 16)
                       | ((uint32_t)fp8b(v.w / scale) << 24);
            *reinterpret_cast<uint32_t*>(g_xq8 + (size_t)row * H_DIM + c) = p;
        }
    } else {
        // ----- w quantize + transpose (register-blocked 4x4) -----
        const int wb = blockIdx.x - QX_BLOCKS;
        const int h0 = (wb & 63) * 64 + (threadIdx.x & 15) * 4;
        const int k0 = (wb >> 6) * 64 + (threadIdx.x >> 4) * 4;

        uint8_t b[4][4];
        #pragma unroll
        for (int j = 0; j < 4; j++) {
            float4 v = *reinterpret_cast<const float4*>(w + (size_t)(k0 + j) * H_DIM + h0);
            b[j][0] = fp8b(v.x); b[j][1] = fp8b(v.y);
            b[j][2] = fp8b(v.z); b[j][3] = fp8b(v.w);
        }
        #pragma unroll
        for (int i = 0; i < 4; i++) {
            uint32_t p = (uint32_t)b[0][i] | ((uint32_t)b[1][i] << 8)
                       | ((uint32_t)b[2][i] << 16) | ((uint32_t)b[3][i] << 24);
            *reinterpret_cast<uint32_t*>(g_wq8t + (size_t)(h0 + i) * H_DIM + k0) = p;
        }
    }
}

// ---------------------------------------------------------------------------
// Kernel 2: fp8 mma.sync GEMM.  y[t,n] = (sum_k xq[t,k]*wqt[n,k]) * xscale[t]*wscale
// CTA 128x128, BK=128, 3-stage cp.async pipeline, 8 warps (2M x 4N), warp 64x32.
// 2 CTAs/SM (launch_bounds reg cap 128) -> 4 warps/SMSP hides LDSM latency.
// ---------------------------------------------------------------------------
#define BM 128
#define BN 128
#define BK 128
#define STAGES 3
#define STG_A (BM * BK)                   // 16384
#define STG_B (BN * BK)                   // 16384
#define STG_BYTES (STG_A + STG_B)         // 32768
#define GEMM_SMEM (1024 + STAGES * STG_BYTES)   // 99328 (2 CTAs/SM: 198656 <= 227KB)

__global__ void __launch_bounds__(256, 2) gemm_f8(float* __restrict__ out,
                                                  const float* __restrict__ wscale_p) {
    extern __shared__ char dyn_smem[];
    const uint32_t base = (smem_u32(dyn_smem) + 1023) & ~1023u;

    const int tid = threadIdx.x;
    const int wid = tid >> 5, lane = tid & 31;
    const int warp_m = wid & 1;     // 2 warps along M (64 rows each)
    const int warp_n = wid >> 1;    // 4 warps along N (32 cols each)

    // 32 consecutive bids share one M-band: A reuse, B fully L2-resident (16MB)
    const int m_tile = blockIdx.x >> 5;     // 0..63
    const int n_tile = blockIdx.x & 31;     // 0..31

    const uint8_t* Ag = g_xq8 + (size_t)m_tile * BM * H_DIM;
    const uint8_t* Bg = g_wq8t + (size_t)n_tile * BN * H_DIM;

    float acc[4][4][4];
    #pragma unroll
    for (int a = 0; a < 4; a++)
        #pragma unroll
        for (int b = 0; b < 4; b++)
            #pragma unroll
            for (int c = 0; c < 4; c++) acc[a][b][c] = 0.f;

    // Load K-slab t into stage s. XOR swizzle (16B chunk ^ row&7) -> conflict-free LDSM.
    auto load_tile = [&](int t, int s) {
        const uint32_t sa = base + s * STG_BYTES;
        const uint32_t sb = sa + STG_A;
        const int koff = t * BK;
        #pragma unroll
        for (int j = 0; j < 4; j++) {           // A: 1024 x 16B
            int idx = tid + j * 256;
            int r = idx >> 3, c = idx & 7;
            CP_ASYNC16(sa + r * 128 + ((c ^ (r & 7)) << 4),
                       Ag + (size_t)r * H_DIM + koff + (c << 4));
        }
        #pragma unroll
        for (int j = 0; j < 4; j++) {           // B: 1024 x 16B
            int idx = tid + j * 256;
            int r = idx >> 3, c = idx & 7;
            CP_ASYNC16(sb + r * 128 + ((c ^ (r & 7)) << 4),
                       Bg + (size_t)r * H_DIM + koff + (c << 4));
        }
        CP_COMMIT();
    };

    const int NKT = H_DIM / BK;   // 32

    // Prologue: fill stages 0..1.
    load_tile(0, 0);
    load_tile(1, 1);

    int s = 0;                     // stage of current tile i
    int ps = STAGES - 1;           // stage of prefetch target (i+2)

    for (int i = 0; i < NKT; i++) {
        CP_WAIT1();              // tile i resident (tile i+1 may be in flight)
        __syncthreads();         // all threads done reading the stage being refilled

        const int nxt = i + STAGES - 1;
        if (nxt < NKT) load_tile(nxt, ps);

        const uint32_t sa = base + s * STG_BYTES;
        const uint32_t sb = sa + STG_A;

        #pragma unroll
        for (int kk = 0; kk < 4; kk++) {        // 4 x k32 per 128B slab
            uint32_t af[4][4];
            #pragma unroll
            for (int mi = 0; mi < 4; mi++) {
                int r = warp_m * 64 + mi * 16 + (lane & 15);
                int ch = (kk * 2 + (lane >> 4)) ^ (r & 7);
                LDMATRIX_X4(af[mi][0], af[mi][1], af[mi][2], af[mi][3],
                            sa + r * 128 + (ch << 4));
            }
            uint32_t bf[4][2];
            #pragma unroll
            for (int g = 0; g < 2; g++) {       // each x4 covers 2 n-groups of 8
                int n = warp_n * 32 + g * 16 + (lane & 15);
                int ch = (kk * 2 + (lane >> 4)) ^ (n & 7);
                uint32_t t0, t1, t2, t3;
                LDMATRIX_X4(t0, t1, t2, t3, sb + n * 128 + (ch << 4));
                bf[g * 2][0] = t0;     bf[g * 2][1] = t2;
                bf[g * 2 + 1][0] = t1; bf[g * 2 + 1][1] = t3;
            }
            #pragma unroll
            for (int mi = 0; mi < 4; mi++)
                #pragma unroll
                for (int ni = 0; ni < 4; ni++)
                    mma_e4m3(acc[mi][ni], af[mi], bf[ni]);
        }

        s = (s == STAGES - 1) ? 0 : s + 1;
        ps = (ps == STAGES - 1) ? 0 : ps + 1;
    }

    // Epilogue: scale by xscale[row]*wscale, store fp32
    const float ws = wscale_p[0];
    const int row_base = m_tile * BM + warp_m * 64;
    const int col_base = n_tile * BN + warp_n * 32;
    #pragma unroll
    for (int mi = 0; mi < 4; mi++) {
        int r0 = row_base + mi * 16 + (lane >> 2);
        float s0 = g_xscale[r0] * ws;
        float s1 = g_xscale[r0 + 8] * ws;
        float* o0 = out + (size_t)r0 * H_DIM + col_base + ((lane & 3) << 1);
        float* o1 = o0 + (size_t)8 * H_DIM;
        #pragma unroll
        for (int ni = 0; ni < 4; ni++) {
            *reinterpret_cast<float2*>(o0 + ni * 8) =
                make_float2(acc[mi][ni][0] * s0, acc[mi][ni][1] * s0);
            *reinterpret_cast<float2*>(o1 + ni * 8) =
                make_float2(acc[mi][ni][2] * s1, acc[mi][ni][3] * s1);
        }
    }
}

// ---------------------------------------------------------------------------
extern "C" void kernel_launch(void* const* d_in, const int* in_sizes, int n_in,
                              void* d_out, int out_size) {
    const float* x = (const float*)d_in[0];        // [8192, 4096] fp32
    const float* w = (const float*)d_in[1];        // [4096, 4096] fp32
    const float* wscale = (const float*)d_in[2];   // [1] fp32
    float* out = (float*)d_out;                    // [8192, 4096] fp32

    cudaFuncSetAttribute(gemm_f8, cudaFuncAttributeMaxDynamicSharedMemorySize, GEMM_SMEM);

    quant_all<<<QX_BLOCKS + QW_BLOCKS, 256>>>(x, w);

    const int num_ctas = (T_DIM / BM) * (H_DIM / BN);  // 64 * 32 = 2048
    gemm_f8<<<num_ctas, 256, GEMM_SMEM>>>(out, wscale);
}

// round 15
// speedup vs baseline: 1.1413x; 1.0249x over previous
#include <cuda_runtime.h>
#include <cuda_bf16.h>
#include <cuda_fp8.h>
#include <cstdint>

// Problem dims (fixed by reference)
#define T_DIM 8192
#define H_DIM 4096            // both K (reduction) and N (output)
#define FP8_MAX_V 448.0f

// ---------------------------------------------------------------------------
// Scratch (allocation-free per harness rules)
// ---------------------------------------------------------------------------
__device__ __align__(16) uint8_t g_xq8[(size_t)T_DIM * H_DIM];    // 32 MB, [t][k] e4m3
__device__ __align__(16) uint8_t g_wq8t[(size_t)H_DIM * H_DIM];   // 16 MB, [n][k] e4m3 (w^T)
__device__ float g_xscale[T_DIM];

// ---------------------------------------------------------------------------
// Helpers
// ---------------------------------------------------------------------------
__device__ __forceinline__ uint32_t smem_u32(const void* p) {
    uint32_t a;
    asm("{ .reg .u64 t; cvta.to.shared.u64 t, %1; cvt.u32.u64 %0, t; }" : "=r"(a) : "l"(p));
    return a;
}

#define CP_ASYNC16(dst, src) \
    asm volatile("cp.async.cg.shared.global [%0], [%1], 16;" :: "r"(dst), "l"(src) : "memory")
#define CP_COMMIT() asm volatile("cp.async.commit_group;" ::: "memory")
#define CP_WAIT1()  asm volatile("cp.async.wait_group 1;" ::: "memory")

#define LDMATRIX_X4(r0, r1, r2, r3, addr) \
    asm volatile("ldmatrix.sync.aligned.m8n8.x4.shared.b16 {%0,%1,%2,%3}, [%4];" \
                 : "=r"(r0), "=r"(r1), "=r"(r2), "=r"(r3) : "r"(addr))

__device__ __forceinline__ void mma_e4m3(float* d, const uint32_t* a, const uint32_t* b) {
    asm volatile(
        "mma.sync.aligned.m16n8k32.row.col.f32.e4m3.e4m3.f32 "
        "{%0,%1,%2,%3}, {%4,%5,%6,%7}, {%8,%9}, {%0,%1,%2,%3};"
        : "+f"(d[0]), "+f"(d[1]), "+f"(d[2]), "+f"(d[3])
        : "r"(a[0]), "r"(a[1]), "r"(a[2]), "r"(a[3]), "r"(b[0]), "r"(b[1]));
}

__device__ __forceinline__ uint8_t fp8b(float v) {
    return (uint8_t)__nv_cvt_float_to_fp8(v, __NV_SATFINITE, __NV_E4M3);
}

// ---------------------------------------------------------------------------
// Kernel 1: fused quantization.
//   blocks [0, 8192):      per-token amax + quantize x row -> g_xq8
//   blocks [8192, 12288):  64x64 w tile quantize+transpose -> g_wq8t
// ---------------------------------------------------------------------------
#define QX_BLOCKS T_DIM                          // 8192
#define QW_BLOCKS ((H_DIM / 64) * (H_DIM / 64))  // 4096

__global__ void __launch_bounds__(256) quant_all(const float* __restrict__ x,
                                                 const float* __restrict__ w) {
    if (blockIdx.x < QX_BLOCKS) {
        // ----- x row quantization -----
        const int row = blockIdx.x;
        const float* xr = x + (size_t)row * H_DIM;

        float amax = 0.f;
        float4 vv[4];
        #pragma unroll
        for (int j = 0; j < 4; j++) {
            vv[j] = *reinterpret_cast<const float4*>(xr + threadIdx.x * 4 + j * 1024);
            amax = fmaxf(amax, fmaxf(fmaxf(fabsf(vv[j].x), fabsf(vv[j].y)),
                                     fmaxf(fabsf(vv[j].z), fabsf(vv[j].w))));
        }
        #pragma unroll
        for (int o = 16; o; o >>= 1)
            amax = fmaxf(amax, __shfl_xor_sync(0xffffffffu, amax, o));

        __shared__ float warpmax[8];
        __shared__ float s_scale;
        int wid = threadIdx.x >> 5, lane = threadIdx.x & 31;
        if (lane == 0) warpmax[wid] = amax;
        __syncthreads();
        if (wid == 0) {
            float m = (lane < 8) ? warpmax[lane] : 0.f;
            #pragma unroll
            for (int o = 4; o; o >>= 1)
                m = fmaxf(m, __shfl_xor_sync(0xffffffffu, m, o));
            if (lane == 0) {
                float s = fmaxf(m / FP8_MAX_V, 1e-12f);
                s_scale = s;
                g_xscale[row] = s;
            }
        }
        __syncthreads();
        const float scale = s_scale;

        #pragma unroll
        for (int j = 0; j < 4; j++) {
            int c = threadIdx.x * 4 + j * 1024;
            float4 v = vv[j];
            uint32_t p = (uint32_t)fp8b(v.x / scale)
                       | ((uint32_t)fp8b(v.y / scale) << 8)
                       | ((uint32_t)fp8b(v.z / scale) << 16)
                       | ((uint32_t)fp8b(v.w / scale) << 24);
            *reinterpret_cast<uint32_t*>(g_xq8 + (size_t)row * H_DIM + c) = p;
        }
    } else {
        // ----- w quantize + transpose (register-blocked 4x4) -----
        const int wb = blockIdx.x - QX_BLOCKS;
        const int h0 = (wb & 63) * 64 + (threadIdx.x & 15) * 4;
        const int k0 = (wb >> 6) * 64 + (threadIdx.x >> 4) * 4;

        uint8_t b[4][4];
        #pragma unroll
        for (int j = 0; j < 4; j++) {
            float4 v = *reinterpret_cast<const float4*>(w + (size_t)(k0 + j) * H_DIM + h0);
            b[j][0] = fp8b(v.x); b[j][1] = fp8b(v.y);
            b[j][2] = fp8b(v.z); b[j][3] = fp8b(v.w);
        }
        #pragma unroll
        for (int i = 0; i < 4; i++) {
            uint32_t p = (uint32_t)b[0][i] | ((uint32_t)b[1][i] << 8)
                       | ((uint32_t)b[2][i] << 16) | ((uint32_t)b[3][i] << 24);
            *reinterpret_cast<uint32_t*>(g_wq8t + (size_t)(h0 + i) * H_DIM + k0) = p;
        }
    }
}

// ---------------------------------------------------------------------------
// Kernel 2: fp8 mma.sync GEMM.  y[t,n] = (sum_k xq[t,k]*wqt[n,k]) * xscale[t]*wscale
// CTA 128x128, BK=128, 3-stage cp.async pipeline, 8 warps (2M x 4N), warp 64x32.
// 2 CTAs/SM. All smem addresses precomputed; per-kk LDSM address = base ^ (kk<<5).
// ---------------------------------------------------------------------------
#define BM 128
#define BN 128
#define BK 128
#define STAGES 3
#define STG_A (BM * BK)                   // 16384
#define STG_B (BN * BK)                   // 16384
#define STG_BYTES (STG_A + STG_B)         // 32768
#define GEMM_SMEM (1024 + STAGES * STG_BYTES)   // 99328 (2 CTAs/SM: 198656)

__global__ void __launch_bounds__(256, 2) gemm_f8(float* __restrict__ out,
                                                  const float* __restrict__ wscale_p) {
    extern __shared__ char dyn_smem[];
    const uint32_t base = (smem_u32(dyn_smem) + 1023) & ~1023u;

    const int tid = threadIdx.x;
    const int wid = tid >> 5, lane = tid & 31;
    const int warp_m = wid & 1;     // 2 warps along M (64 rows each)
    const int warp_n = wid >> 1;    // 4 warps along N (32 cols each)

    // 32 consecutive bids share one M-band: A reuse, B fully L2-resident (16MB)
    const int m_tile = blockIdx.x >> 5;     // 0..63
    const int n_tile = blockIdx.x & 31;     // 0..31

    const uint8_t* Ag = g_xq8 + (size_t)m_tile * BM * H_DIM;
    const uint8_t* Bg = g_wq8t + (size_t)n_tile * BN * H_DIM;

    // ---- Precomputed cp.async addressing (per thread, fixed all loop) ----
    // 4 A-copies + 4 B-copies per thread per slab.
    uint32_t dst_off[4];     // swizzled dst offset within a stage (A; B adds STG_A)
    uint32_t src_off[4];     // byte offset within the A/B panel (same r,c for both)
    #pragma unroll
    for (int j = 0; j < 4; j++) {
        int idx = tid + j * 256;
        int r = idx >> 3, c = idx & 7;
        dst_off[j] = r * 128 + ((c ^ (r & 7)) << 4);
        src_off[j] = (uint32_t)(r * H_DIM + (c << 4));
    }

    // ---- Precomputed LDSM base offsets (kk=0); per-kk address = base ^ (kk<<5)
    // ch(kk) = ((kk<<1)|hi) ^ r7 = ch(0) ^ (kk<<1)  (disjoint bits, XOR-composable)
    const int hi = lane >> 4;
    uint32_t a_off[4], b_off[2];
    #pragma unroll
    for (int mi = 0; mi < 4; mi++) {
        int r = warp_m * 64 + mi * 16 + (lane & 15);
        a_off[mi] = r * 128 + ((hi ^ (r & 7)) << 4);
    }
    #pragma unroll
    for (int g = 0; g < 2; g++) {
        int n = warp_n * 32 + g * 16 + (lane & 15);
        b_off[g] = STG_A + n * 128 + ((hi ^ (n & 7)) << 4);
    }

    float acc[4][4][4];
    #pragma unroll
    for (int a = 0; a < 4; a++)
        #pragma unroll
        for (int b = 0; b < 4; b++)
            #pragma unroll
            for (int c = 0; c < 4; c++) acc[a][b][c] = 0.f;

    // Load K-slab at byte offset koff into stage s: 2 IADD per copy.
    auto load_tile = [&](uint32_t koff, int s) {
        const uint32_t sa = base + s * STG_BYTES;
        #pragma unroll
        for (int j = 0; j < 4; j++)
            CP_ASYNC16(sa + dst_off[j], Ag + src_off[j] + koff);
        #pragma unroll
        for (int j = 0; j < 4; j++)
            CP_ASYNC16(sa + STG_A + dst_off[j], Bg + src_off[j] + koff);
        CP_COMMIT();
    };

    const int NKT = H_DIM / BK;   // 32

    load_tile(0, 0);
    load_tile(BK, 1);

    int s = 0;                     // stage of current tile i
    int ps = STAGES - 1;           // stage of prefetch target (i+2)
    uint32_t pkoff = (uint32_t)(STAGES - 1) * BK;

    for (int i = 0; i < NKT; i++) {
        CP_WAIT1();              // tile i resident (tile i+1 may be in flight)
        __syncthreads();         // all threads done reading the stage being refilled

        if (i + STAGES - 1 < NKT) {
            load_tile(pkoff, ps);
            pkoff += BK;
        }

        const uint32_t sa = base + s * STG_BYTES;
        // Per-slab LDSM base addresses (6 IADD, hoisted out of kk loop)
        uint32_t aadr[4], badr[2];
        #pragma unroll
        for (int mi = 0; mi < 4; mi++) aadr[mi] = sa + a_off[mi];
        #pragma unroll
        for (int g = 0; g < 2; g++)    badr[g] = sa + b_off[g];

        #pragma unroll
        for (int kk = 0; kk < 4; kk++) {        // 4 x k32 per 128B slab
            const uint32_t kx = (uint32_t)kk << 5;   // immediate after unroll
            uint32_t af[4][4];
            #pragma unroll
            for (int mi = 0; mi < 4; mi++)
                LDMATRIX_X4(af[mi][0], af[mi][1], af[mi][2], af[mi][3],
                            aadr[mi] ^ kx);
            uint32_t bf[4][2];
            #pragma unroll
            for (int g = 0; g < 2; g++) {       // each x4 covers 2 n-groups of 8
                uint32_t t0, t1, t2, t3;
                LDMATRIX_X4(t0, t1, t2, t3, badr[g] ^ kx);
                bf[g * 2][0] = t0;     bf[g * 2][1] = t2;
                bf[g * 2 + 1][0] = t1; bf[g * 2 + 1][1] = t3;
            }
            #pragma unroll
            for (int mi = 0; mi < 4; mi++)
                #pragma unroll
                for (int ni = 0; ni < 4; ni++)
                    mma_e4m3(acc[mi][ni], af[mi], bf[ni]);
        }

        s = (s == STAGES - 1) ? 0 : s + 1;
        ps = (ps == STAGES - 1) ? 0 : ps + 1;
    }

    // Epilogue: scale by xscale[row]*wscale, store fp32
    const float ws = wscale_p[0];
    const int row_base = m_tile * BM + warp_m * 64;
    const int col_base = n_tile * BN + warp_n * 32;
    #pragma unroll
    for (int mi = 0; mi < 4; mi++) {
        int r0 = row_base + mi * 16 + (lane >> 2);
        float s0 = g_xscale[r0] * ws;
        float s1 = g_xscale[r0 + 8] * ws;
        float* o0 = out + (size_t)r0 * H_DIM + col_base + ((lane & 3) << 1);
        float* o1 = o0 + (size_t)8 * H_DIM;
        #pragma unroll
        for (int ni = 0; ni < 4; ni++) {
            *reinterpret_cast<float2*>(o0 + ni * 8) =
                make_float2(acc[mi][ni][0] * s0, acc[mi][ni][1] * s0);
            *reinterpret_cast<float2*>(o1 + ni * 8) =
                make_float2(acc[mi][ni][2] * s1, acc[mi][ni][3] * s1);
        }
    }
}

// ---------------------------------------------------------------------------
extern "C" void kernel_launch(void* const* d_in, const int* in_sizes, int n_in,
                              void* d_out, int out_size) {
    const float* x = (const float*)d_in[0];        // [8192, 4096] fp32
    const float* w = (const float*)d_in[1];        // [4096, 4096] fp32
    const float* wscale = (const float*)d_in[2];   // [1] fp32
    float* out = (float*)d_out;                    // [8192, 4096] fp32

    cudaFuncSetAttribute(gemm_f8, cudaFuncAttributeMaxDynamicSharedMemorySize, GEMM_SMEM);

    quant_all<<<QX_BLOCKS + QW_BLOCKS, 256>>>(x, w);

    const int num_ctas = (T_DIM / BM) * (H_DIM / BN);  // 64 * 32 = 2048
    gemm_f8<<<num_ctas, 256, GEMM_SMEM>>>(out, wscale);
}